// round 5
// baseline (speedup 1.0000x reference)
#include <cuda_runtime.h>
#include <cstddef>

#define T_SEQ 2048
#define C_EMB 1024
#define NH    16
#define HS    64
#define BATCH 4

// Scratch (device globals — no runtime allocation allowed)
__device__ float g_qkv[(size_t)BATCH * T_SEQ * 3 * C_EMB]; // 96 MB
__device__ float g_y[(size_t)BATCH * T_SEQ * C_EMB];       // 32 MB

// ---------------------------------------------------------------------------
// Classic 128x128x8 register-blocked SGEMM (row-major A[MxK] @ B[KxN] = C[MxN])
// Requires M%128==0, N%128==0, K%8==0 (true for all shapes here).
// ---------------------------------------------------------------------------
__global__ __launch_bounds__(256) void sgemm_kernel(
    const float* __restrict__ A, const float* __restrict__ B,
    float* __restrict__ C, int M, int N, int K)
{
    constexpr int BM = 128, BN = 128, BK = 8, TM = 8, TN = 8;
    __shared__ float As[BK][BM];
    __shared__ float Bs[BK][BN];

    const int tid = threadIdx.x;
    const int row0 = blockIdx.y * BM;
    const int col0 = blockIdx.x * BN;

    // Load mappings: one float4 per thread per tile for A and for B
    const int arow = tid >> 1;            // 0..127
    const int acol = (tid & 1) * 4;       // 0 or 4
    const int brow = tid >> 5;            // 0..7
    const int bcol = (tid & 31) * 4;      // 0..124

    const float* Aptr = A + (size_t)(row0 + arow) * K + acol;
    const float* Bptr = B + (size_t)brow * N + col0 + bcol;

    float acc[TM][TN];
#pragma unroll
    for (int i = 0; i < TM; i++)
#pragma unroll
        for (int j = 0; j < TN; j++) acc[i][j] = 0.f;

    const int tx = tid & 15;   // 0..15
    const int ty = tid >> 4;   // 0..15

    for (int kt = 0; kt < K; kt += BK) {
        float4 av = *(const float4*)(Aptr + kt);
        float4 bv = *(const float4*)(Bptr + (size_t)kt * N);
        As[acol + 0][arow] = av.x;
        As[acol + 1][arow] = av.y;
        As[acol + 2][arow] = av.z;
        As[acol + 3][arow] = av.w;
        *(float4*)&Bs[brow][bcol] = bv;
        __syncthreads();

#pragma unroll
        for (int k = 0; k < BK; k++) {
            float ar[TM], br[TN];
            const float4 a0 = *(const float4*)&As[k][ty * TM];
            const float4 a1 = *(const float4*)&As[k][ty * TM + 4];
            ar[0]=a0.x; ar[1]=a0.y; ar[2]=a0.z; ar[3]=a0.w;
            ar[4]=a1.x; ar[5]=a1.y; ar[6]=a1.z; ar[7]=a1.w;
            const float4 b0 = *(const float4*)&Bs[k][tx * TN];
            const float4 b1 = *(const float4*)&Bs[k][tx * TN + 4];
            br[0]=b0.x; br[1]=b0.y; br[2]=b0.z; br[3]=b0.w;
            br[4]=b1.x; br[5]=b1.y; br[6]=b1.z; br[7]=b1.w;
#pragma unroll
            for (int i = 0; i < TM; i++)
#pragma unroll
                for (int j = 0; j < TN; j++)
                    acc[i][j] += ar[i] * br[j];
        }
        __syncthreads();
    }

#pragma unroll
    for (int i = 0; i < TM; i++) {
        float* crow = C + (size_t)(row0 + ty * TM + i) * N + col0 + tx * TN;
        float4 c0 = make_float4(acc[i][0], acc[i][1], acc[i][2], acc[i][3]);
        float4 c1 = make_float4(acc[i][4], acc[i][5], acc[i][6], acc[i][7]);
        *(float4*)(crow)     = c0;
        *(float4*)(crow + 4) = c1;
    }
}

// ---------------------------------------------------------------------------
// Flash attention, fp32, causal. One thread = one query row.
// Block: 128 threads = 128 queries of one (b, h). KV tiles of 32 rows in smem.
// q[64], o[64], s[32] fully register-resident (all index loops unrolled).
// ---------------------------------------------------------------------------
__global__ __launch_bounds__(128) void attn_kernel(
    const float* __restrict__ qkv, float* __restrict__ y)
{
    const int b  = blockIdx.z;
    const int h  = blockIdx.y;
    const int q0 = blockIdx.x * 128;
    const int tid = threadIdx.x;
    const int qi = q0 + tid;

    const float* base = qkv + (size_t)b * T_SEQ * 3 * C_EMB;
    const int koff = C_EMB + h * HS;
    const int voff = 2 * C_EMB + h * HS;

    float q[HS];
    {
        const float* qrow = base + (size_t)qi * 3 * C_EMB + h * HS;
#pragma unroll
        for (int d = 0; d < HS; d++) q[d] = qrow[d] * 0.125f; // hs^-0.5 = 1/8
    }

    float o[HS];
#pragma unroll
    for (int d = 0; d < HS; d++) o[d] = 0.f;
    float m = -1e30f, l = 0.f;

    __shared__ float Ks[32][HS];
    __shared__ float Vs[32][HS];

    const int kv_end = q0 + 128; // max key index needed by this block (exclusive)

    for (int k0 = 0; k0 < kv_end; k0 += 32) {
        __syncthreads();
        // Cooperative load of K/V tile: 32 rows x 64 cols -> 512 float4 each
#pragma unroll
        for (int i = 0; i < 4; i++) {
            int idx = tid + i * 128;       // 0..511
            int row = idx >> 4;            // 0..31
            int d4  = (idx & 15) * 4;      // 0..60
            const float* src = base + (size_t)(k0 + row) * 3 * C_EMB;
            *(float4*)&Ks[row][d4] = *(const float4*)(src + koff + d4);
            *(float4*)&Vs[row][d4] = *(const float4*)(src + voff + d4);
        }
        __syncthreads();

        float s[32];
#pragma unroll
        for (int j = 0; j < 32; j++) {
            const float4* krow = (const float4*)Ks[j];
            float acc = 0.f;
#pragma unroll
            for (int d4 = 0; d4 < 16; d4++) {
                float4 k4 = krow[d4];
                acc += q[d4 * 4 + 0] * k4.x;
                acc += q[d4 * 4 + 1] * k4.y;
                acc += q[d4 * 4 + 2] * k4.z;
                acc += q[d4 * 4 + 3] * k4.w;
            }
            s[j] = (k0 + j <= qi) ? acc : -1e30f;
        }

        float mt = m;
#pragma unroll
        for (int j = 0; j < 32; j++) mt = fmaxf(mt, s[j]);
        const float corr = __expf(m - mt);
        m = mt;

        float psum = 0.f;
#pragma unroll
        for (int j = 0; j < 32; j++) {
            s[j] = __expf(s[j] - mt);
            psum += s[j];
        }
        l = l * corr + psum;

#pragma unroll
        for (int d = 0; d < HS; d++) o[d] *= corr;

#pragma unroll
        for (int j = 0; j < 32; j++) {
            const float pj = s[j];
            const float4* vrow = (const float4*)Vs[j];
#pragma unroll
            for (int d4 = 0; d4 < 16; d4++) {
                float4 v4 = vrow[d4];
                o[d4 * 4 + 0] += pj * v4.x;
                o[d4 * 4 + 1] += pj * v4.y;
                o[d4 * 4 + 2] += pj * v4.z;
                o[d4 * 4 + 3] += pj * v4.w;
            }
        }
    }

    const float inv_l = 1.0f / l;
    float* yrow = y + (size_t)(b * T_SEQ + qi) * C_EMB + h * HS;
#pragma unroll
    for (int d4 = 0; d4 < 16; d4++) {
        float4 v = make_float4(o[d4*4+0]*inv_l, o[d4*4+1]*inv_l,
                               o[d4*4+2]*inv_l, o[d4*4+3]*inv_l);
        *(float4*)(yrow + d4 * 4) = v;
    }
}

// ---------------------------------------------------------------------------
extern "C" void kernel_launch(void* const* d_in, const int* in_sizes, int n_in,
                              void* d_out, int out_size)
{
    const float* x      = (const float*)d_in[0];
    const float* w_attn = (const float*)d_in[1];
    const float* w_proj = (const float*)d_in[2];
    float* out = (float*)d_out;

    float* qkv = nullptr;
    float* y   = nullptr;
    cudaGetSymbolAddress((void**)&qkv, g_qkv);
    cudaGetSymbolAddress((void**)&y,   g_y);

    const int M = BATCH * T_SEQ;        // 8192
    const int C = C_EMB;                // 1024

    // 1) QKV projection: [8192,1024] @ [1024,3072]
    {
        dim3 grid((3 * C) / 128, M / 128);
        sgemm_kernel<<<grid, 256>>>(x, w_attn, qkv, M, 3 * C, C);
    }
    // 2) Causal flash attention
    {
        dim3 grid(T_SEQ / 128, NH, BATCH);
        attn_kernel<<<grid, 128>>>(qkv, y);
    }
    // 3) Output projection: [8192,1024] @ [1024,1024]
    {
        dim3 grid(C / 128, M / 128);
        sgemm_kernel<<<grid, 256>>>(y, w_proj, out, M, C, C);
    }
}

// round 7
// speedup vs baseline: 1.4135x; 1.4135x over previous
#include <cuda_runtime.h>
#include <cstddef>

#define T_SEQ 2048
#define C_EMB 1024
#define NH    16
#define HS    64
#define BATCH 4

// Scratch (device globals — no runtime allocation allowed)
__device__ float g_qkv[(size_t)BATCH * T_SEQ * 3 * C_EMB]; // 96 MB
__device__ float g_y[(size_t)BATCH * T_SEQ * C_EMB];       // 32 MB

__device__ __forceinline__ unsigned f2tf(float f) {
    unsigned u;
    asm("cvt.rna.tf32.f32 %0, %1;" : "=r"(u) : "f"(f));
    return u;
}

// ---------------------------------------------------------------------------
// tf32 tensor-core GEMM: C[MxN] = A[MxK] @ B[KxN], all row-major fp32.
// Block tile 128x128x16, 256 threads (8 warps in 2x4), warp tile 64x32.
// mma.sync.aligned.m16n8k8.row.col.f32.tf32.tf32.f32
// Requires M%128==0, N%128==0, K%16==0.
// ---------------------------------------------------------------------------
__global__ __launch_bounds__(256) void tf32_gemm(
    const float* __restrict__ A, const float* __restrict__ B,
    float* __restrict__ C, int M, int N, int K)
{
    constexpr int BM = 128, BN = 128, BK = 16;
    constexpr int LDS_PAD = 136; // (c*8+g)%32 -> conflict-free fragment loads
    __shared__ unsigned As[BK][LDS_PAD];
    __shared__ unsigned Bs[BK][LDS_PAD];

    const int tid  = threadIdx.x;
    const int lane = tid & 31;
    const int warp = tid >> 5;
    const int wm = warp & 1;   // 0..1  (64-row slab)
    const int wn = warp >> 1;  // 0..3  (32-col slab)
    const int g = lane >> 2;   // 0..7
    const int c = lane & 3;    // 0..3

    const int row0 = blockIdx.y * BM;
    const int col0 = blockIdx.x * BN;

    // Global-load mapping
    const int arow = tid >> 1;          // 0..127
    const int acol = (tid & 1) * 8;     // 0 or 8
    const int brow = tid >> 4;          // 0..15
    const int bcol = (tid & 15) * 8;    // 0..120

    const float* Ap = A + (size_t)(row0 + arow) * K + acol;
    const float* Bp = B + (size_t)brow * N + col0 + bcol;

    float acc[4][4][4];
#pragma unroll
    for (int i = 0; i < 4; i++)
#pragma unroll
        for (int j = 0; j < 4; j++)
#pragma unroll
            for (int r = 0; r < 4; r++) acc[i][j][r] = 0.f;

    const int ntiles = K / BK;

    float4 a0v = *(const float4*)(Ap);
    float4 a1v = *(const float4*)(Ap + 4);
    float4 b0v = *(const float4*)(Bp);
    float4 b1v = *(const float4*)(Bp + 4);

    for (int kt = 0; kt < ntiles; kt++) {
        // Store current tile to smem (A transposed to [k][m], tf32-converted)
        As[acol + 0][arow] = f2tf(a0v.x);
        As[acol + 1][arow] = f2tf(a0v.y);
        As[acol + 2][arow] = f2tf(a0v.z);
        As[acol + 3][arow] = f2tf(a0v.w);
        As[acol + 4][arow] = f2tf(a1v.x);
        As[acol + 5][arow] = f2tf(a1v.y);
        As[acol + 6][arow] = f2tf(a1v.z);
        As[acol + 7][arow] = f2tf(a1v.w);
        {
            uint4 p0 = make_uint4(f2tf(b0v.x), f2tf(b0v.y), f2tf(b0v.z), f2tf(b0v.w));
            uint4 p1 = make_uint4(f2tf(b1v.x), f2tf(b1v.y), f2tf(b1v.z), f2tf(b1v.w));
            *(uint4*)&Bs[brow][bcol]     = p0;
            *(uint4*)&Bs[brow][bcol + 4] = p1;
        }
        __syncthreads();

        // Prefetch next tile into registers
        if (kt + 1 < ntiles) {
            const float* Ap2 = Ap + (kt + 1) * BK;
            const float* Bp2 = Bp + (size_t)(kt + 1) * BK * N;
            a0v = *(const float4*)(Ap2);
            a1v = *(const float4*)(Ap2 + 4);
            b0v = *(const float4*)(Bp2);
            b1v = *(const float4*)(Bp2 + 4);
        }

        // Compute: 2 k-steps of k8
#pragma unroll
        for (int s = 0; s < 2; s++) {
            const int k0 = s * 8;
            unsigned af[4][4];
            unsigned bf[4][2];
#pragma unroll
            for (int i = 0; i < 4; i++) {
                const int m = wm * 64 + i * 16 + g;
                af[i][0] = As[k0 + c][m];
                af[i][1] = As[k0 + c][m + 8];
                af[i][2] = As[k0 + c + 4][m];
                af[i][3] = As[k0 + c + 4][m + 8];
            }
#pragma unroll
            for (int j = 0; j < 4; j++) {
                const int n = wn * 32 + j * 8 + g;
                bf[j][0] = Bs[k0 + c][n];
                bf[j][1] = Bs[k0 + c + 4][n];
            }
#pragma unroll
            for (int i = 0; i < 4; i++)
#pragma unroll
                for (int j = 0; j < 4; j++) {
                    asm volatile(
                        "mma.sync.aligned.m16n8k8.row.col.f32.tf32.tf32.f32 "
                        "{%0,%1,%2,%3}, {%4,%5,%6,%7}, {%8,%9}, {%0,%1,%2,%3};"
                        : "+f"(acc[i][j][0]), "+f"(acc[i][j][1]),
                          "+f"(acc[i][j][2]), "+f"(acc[i][j][3])
                        : "r"(af[i][0]), "r"(af[i][1]), "r"(af[i][2]), "r"(af[i][3]),
                          "r"(bf[j][0]), "r"(bf[j][1]));
                }
        }
        __syncthreads();
    }

    // Epilogue: float2 stores
#pragma unroll
    for (int i = 0; i < 4; i++) {
        const int r = row0 + wm * 64 + i * 16 + g;
#pragma unroll
        for (int j = 0; j < 4; j++) {
            const int cc = col0 + wn * 32 + j * 8 + 2 * c;
            float2 lo = make_float2(acc[i][j][0], acc[i][j][1]);
            float2 hi = make_float2(acc[i][j][2], acc[i][j][3]);
            *(float2*)(C + (size_t)r * N + cc)       = lo;
            *(float2*)(C + (size_t)(r + 8) * N + cc) = hi;
        }
    }
}

// ---------------------------------------------------------------------------
// Flash attention, fp32, causal. One thread = one query row. (unchanged)
// ---------------------------------------------------------------------------
__global__ __launch_bounds__(128) void attn_kernel(
    const float* __restrict__ qkv, float* __restrict__ y)
{
    const int b  = blockIdx.z;
    const int h  = blockIdx.y;
    const int q0 = blockIdx.x * 128;
    const int tid = threadIdx.x;
    const int qi = q0 + tid;

    const float* base = qkv + (size_t)b * T_SEQ * 3 * C_EMB;
    const int koff = C_EMB + h * HS;
    const int voff = 2 * C_EMB + h * HS;

    float q[HS];
    {
        const float* qrow = base + (size_t)qi * 3 * C_EMB + h * HS;
#pragma unroll
        for (int d = 0; d < HS; d++) q[d] = qrow[d] * 0.125f;
    }

    float o[HS];
#pragma unroll
    for (int d = 0; d < HS; d++) o[d] = 0.f;
    float m = -1e30f, l = 0.f;

    __shared__ float Ks[32][HS];
    __shared__ float Vs[32][HS];

    const int kv_end = q0 + 128;

    for (int k0 = 0; k0 < kv_end; k0 += 32) {
        __syncthreads();
#pragma unroll
        for (int i = 0; i < 4; i++) {
            int idx = tid + i * 128;
            int row = idx >> 4;
            int d4  = (idx & 15) * 4;
            const float* src = base + (size_t)(k0 + row) * 3 * C_EMB;
            *(float4*)&Ks[row][d4] = *(const float4*)(src + koff + d4);
            *(float4*)&Vs[row][d4] = *(const float4*)(src + voff + d4);
        }
        __syncthreads();

        float s[32];
#pragma unroll
        for (int j = 0; j < 32; j++) {
            const float4* krow = (const float4*)Ks[j];
            float acc = 0.f;
#pragma unroll
            for (int d4 = 0; d4 < 16; d4++) {
                float4 k4 = krow[d4];
                acc += q[d4 * 4 + 0] * k4.x;
                acc += q[d4 * 4 + 1] * k4.y;
                acc += q[d4 * 4 + 2] * k4.z;
                acc += q[d4 * 4 + 3] * k4.w;
            }
            s[j] = (k0 + j <= qi) ? acc : -1e30f;
        }

        float mt = m;
#pragma unroll
        for (int j = 0; j < 32; j++) mt = fmaxf(mt, s[j]);
        const float corr = __expf(m - mt);
        m = mt;

        float psum = 0.f;
#pragma unroll
        for (int j = 0; j < 32; j++) {
            s[j] = __expf(s[j] - mt);
            psum += s[j];
        }
        l = l * corr + psum;

#pragma unroll
        for (int d = 0; d < HS; d++) o[d] *= corr;

#pragma unroll
        for (int j = 0; j < 32; j++) {
            const float pj = s[j];
            const float4* vrow = (const float4*)Vs[j];
#pragma unroll
            for (int d4 = 0; d4 < 16; d4++) {
                float4 v4 = vrow[d4];
                o[d4 * 4 + 0] += pj * v4.x;
                o[d4 * 4 + 1] += pj * v4.y;
                o[d4 * 4 + 2] += pj * v4.z;
                o[d4 * 4 + 3] += pj * v4.w;
            }
        }
    }

    const float inv_l = 1.0f / l;
    float* yrow = y + (size_t)(b * T_SEQ + qi) * C_EMB + h * HS;
#pragma unroll
    for (int d4 = 0; d4 < 16; d4++) {
        float4 v = make_float4(o[d4*4+0]*inv_l, o[d4*4+1]*inv_l,
                               o[d4*4+2]*inv_l, o[d4*4+3]*inv_l);
        *(float4*)(yrow + d4 * 4) = v;
    }
}

// ---------------------------------------------------------------------------
extern "C" void kernel_launch(void* const* d_in, const int* in_sizes, int n_in,
                              void* d_out, int out_size)
{
    const float* x      = (const float*)d_in[0];
    const float* w_attn = (const float*)d_in[1];
    const float* w_proj = (const float*)d_in[2];
    float* out = (float*)d_out;

    float* qkv = nullptr;
    float* y   = nullptr;
    cudaGetSymbolAddress((void**)&qkv, g_qkv);
    cudaGetSymbolAddress((void**)&y,   g_y);

    const int M = BATCH * T_SEQ;        // 8192
    const int C = C_EMB;                // 1024

    // 1) QKV projection: [8192,1024] @ [1024,3072]  (tf32 tensor cores)
    {
        dim3 grid((3 * C) / 128, M / 128);
        tf32_gemm<<<grid, 256>>>(x, w_attn, qkv, M, 3 * C, C);
    }
    // 2) Causal flash attention (fp32)
    {
        dim3 grid(T_SEQ / 128, NH, BATCH);
        attn_kernel<<<grid, 128>>>(qkv, y);
    }
    // 3) Output projection: [8192,1024] @ [1024,1024]  (tf32 tensor cores)
    {
        dim3 grid(C / 128, M / 128);
        tf32_gemm<<<grid, 256>>>(y, w_proj, out, M, C, C);
    }
}

// round 10
// speedup vs baseline: 3.5441x; 2.5073x over previous
#include <cuda_runtime.h>
#include <cstddef>

#define T_SEQ 2048
#define C_EMB 1024
#define NH    16
#define HS    64
#define BATCH 4

// Scratch (device globals — no runtime allocation allowed)
__device__ float g_qkv[(size_t)BATCH * T_SEQ * 3 * C_EMB]; // 96 MB
__device__ float g_y[(size_t)BATCH * T_SEQ * C_EMB];       // 32 MB

__device__ __forceinline__ unsigned f2tf(float f) {
    unsigned u;
    asm("cvt.rna.tf32.f32 %0, %1;" : "=r"(u) : "f"(f));
    return u;
}

__device__ __forceinline__ void mma_tf32(
    float* acc, const unsigned* a, unsigned b0, unsigned b1)
{
    asm volatile(
        "mma.sync.aligned.m16n8k8.row.col.f32.tf32.tf32.f32 "
        "{%0,%1,%2,%3}, {%4,%5,%6,%7}, {%8,%9}, {%0,%1,%2,%3};"
        : "+f"(acc[0]), "+f"(acc[1]), "+f"(acc[2]), "+f"(acc[3])
        : "r"(a[0]), "r"(a[1]), "r"(a[2]), "r"(a[3]), "r"(b0), "r"(b1));
}

// ---------------------------------------------------------------------------
// tf32 tensor-core GEMM: C[MxN] = A[MxK] @ B[KxN], all row-major fp32.
// Block tile 128x128x16, 256 threads (8 warps in 2x4), warp tile 64x32.
// ---------------------------------------------------------------------------
__global__ __launch_bounds__(256) void tf32_gemm(
    const float* __restrict__ A, const float* __restrict__ B,
    float* __restrict__ C, int M, int N, int K)
{
    constexpr int BM = 128, BN = 128, BK = 16;
    constexpr int LDS_PAD = 136;
    __shared__ unsigned As[BK][LDS_PAD];
    __shared__ unsigned Bs[BK][LDS_PAD];

    const int tid  = threadIdx.x;
    const int lane = tid & 31;
    const int warp = tid >> 5;
    const int wm = warp & 1;
    const int wn = warp >> 1;
    const int g = lane >> 2;
    const int c = lane & 3;

    const int row0 = blockIdx.y * BM;
    const int col0 = blockIdx.x * BN;

    const int arow = tid >> 1;
    const int acol = (tid & 1) * 8;
    const int brow = tid >> 4;
    const int bcol = (tid & 15) * 8;

    const float* Ap = A + (size_t)(row0 + arow) * K + acol;
    const float* Bp = B + (size_t)brow * N + col0 + bcol;

    float acc[4][4][4];
#pragma unroll
    for (int i = 0; i < 4; i++)
#pragma unroll
        for (int j = 0; j < 4; j++)
#pragma unroll
            for (int r = 0; r < 4; r++) acc[i][j][r] = 0.f;

    const int ntiles = K / BK;

    float4 a0v = *(const float4*)(Ap);
    float4 a1v = *(const float4*)(Ap + 4);
    float4 b0v = *(const float4*)(Bp);
    float4 b1v = *(const float4*)(Bp + 4);

    for (int kt = 0; kt < ntiles; kt++) {
        As[acol + 0][arow] = f2tf(a0v.x);
        As[acol + 1][arow] = f2tf(a0v.y);
        As[acol + 2][arow] = f2tf(a0v.z);
        As[acol + 3][arow] = f2tf(a0v.w);
        As[acol + 4][arow] = f2tf(a1v.x);
        As[acol + 5][arow] = f2tf(a1v.y);
        As[acol + 6][arow] = f2tf(a1v.z);
        As[acol + 7][arow] = f2tf(a1v.w);
        {
            uint4 p0 = make_uint4(f2tf(b0v.x), f2tf(b0v.y), f2tf(b0v.z), f2tf(b0v.w));
            uint4 p1 = make_uint4(f2tf(b1v.x), f2tf(b1v.y), f2tf(b1v.z), f2tf(b1v.w));
            *(uint4*)&Bs[brow][bcol]     = p0;
            *(uint4*)&Bs[brow][bcol + 4] = p1;
        }
        __syncthreads();

        if (kt + 1 < ntiles) {
            const float* Ap2 = Ap + (kt + 1) * BK;
            const float* Bp2 = Bp + (size_t)(kt + 1) * BK * N;
            a0v = *(const float4*)(Ap2);
            a1v = *(const float4*)(Ap2 + 4);
            b0v = *(const float4*)(Bp2);
            b1v = *(const float4*)(Bp2 + 4);
        }

#pragma unroll
        for (int s = 0; s < 2; s++) {
            const int k0 = s * 8;
            unsigned af[4][4];
            unsigned bf[4][2];
#pragma unroll
            for (int i = 0; i < 4; i++) {
                const int m = wm * 64 + i * 16 + g;
                af[i][0] = As[k0 + c][m];
                af[i][1] = As[k0 + c][m + 8];
                af[i][2] = As[k0 + c + 4][m];
                af[i][3] = As[k0 + c + 4][m + 8];
            }
#pragma unroll
            for (int j = 0; j < 4; j++) {
                const int n = wn * 32 + j * 8 + g;
                bf[j][0] = Bs[k0 + c][n];
                bf[j][1] = Bs[k0 + c + 4][n];
            }
#pragma unroll
            for (int i = 0; i < 4; i++)
#pragma unroll
                for (int j = 0; j < 4; j++)
                    mma_tf32(acc[i][j], af[i], bf[j][0], bf[j][1]);
        }
        __syncthreads();
    }

#pragma unroll
    for (int i = 0; i < 4; i++) {
        const int r = row0 + wm * 64 + i * 16 + g;
#pragma unroll
        for (int j = 0; j < 4; j++) {
            const int cc = col0 + wn * 32 + j * 8 + 2 * c;
            float2 lo = make_float2(acc[i][j][0], acc[i][j][1]);
            float2 hi = make_float2(acc[i][j][2], acc[i][j][3]);
            *(float2*)(C + (size_t)r * N + cc)       = lo;
            *(float2*)(C + (size_t)(r + 8) * N + cc) = hi;
        }
    }
}

// ---------------------------------------------------------------------------
// Tensor-core causal flash attention (tf32 mma, fp32 softmax/accum).
// Block = 128 queries of one (b,h); 8 warps, each owns one m16 tile.
// Key tiles of 64 staged in smem (tf32). Q fragments register-resident.
// ---------------------------------------------------------------------------
__global__ __launch_bounds__(256) void attn_tc(
    const float* __restrict__ qkv, float* __restrict__ y)
{
    const int b  = blockIdx.z;
    const int h  = blockIdx.y;
    const int q0 = blockIdx.x * 128;
    const int tid  = threadIdx.x;
    const int lane = tid & 31;
    const int warp = tid >> 5;
    const int g = lane >> 2;
    const int c = lane & 3;

    // Pads chosen for conflict-free fragment reads:
    //   Ks[key][dim] pad 68: frag addr (8j+g)*68 + 8t+c  -> banks 4g+c (bijective)
    //   Vs[key][dim] pad 72: frag addr (8t+c)*72 + 8j+g  -> banks 8c+g (bijective)
    __shared__ __align__(16) unsigned Ks[64 * 68];
    __shared__ __align__(16) unsigned Vs[64 * 72];

    const float* base = qkv + (size_t)b * T_SEQ * 3 * C_EMB;
    const int koff = C_EMB + h * HS;
    const int voff = 2 * C_EMB + h * HS;

    // Q fragments, pre-scaled by hs^-0.5 = 0.125, tf32. Rows qi0=q0+16w+g, qi1=qi0+8.
    unsigned Qf[8][4];
    {
        const float* qb = base + (size_t)(q0 + warp * 16) * 3 * C_EMB + h * HS;
        const int r0 = g * 3 * C_EMB;
        const int r1 = (g + 8) * 3 * C_EMB;
#pragma unroll
        for (int t = 0; t < 8; t++) {
            Qf[t][0] = f2tf(qb[r0 + 8 * t + c]     * 0.125f);
            Qf[t][1] = f2tf(qb[r1 + 8 * t + c]     * 0.125f);
            Qf[t][2] = f2tf(qb[r0 + 8 * t + c + 4] * 0.125f);
            Qf[t][3] = f2tf(qb[r1 + 8 * t + c + 4] * 0.125f);
        }
    }

    float Of[8][4];
#pragma unroll
    for (int j = 0; j < 8; j++)
#pragma unroll
        for (int r = 0; r < 4; r++) Of[j][r] = 0.f;

    float m0 = -1e30f, m1 = -1e30f, l0 = 0.f, l1 = 0.f;
    const int qi0 = q0 + warp * 16 + g;
    const int qi1 = qi0 + 8;

    const int srcA = (g << 2) + (c >> 1);
    const int srcB = srcA + 2;
    const bool sel = (c & 1) != 0;

    const int kv_end = q0 + 128;
    for (int k0 = 0; k0 < kv_end; k0 += 64) {
        __syncthreads();
        // Cooperative K/V tile load: 64 keys x 64 dims, tf32-converted.
#pragma unroll
        for (int i = 0; i < 4; i++) {
            int idx = tid + i * 256;
            int key = idx >> 4;
            int d4  = (idx & 15) << 2;
            const float* src = base + (size_t)(k0 + key) * 3 * C_EMB;
            float4 k4 = *(const float4*)(src + koff + d4);
            float4 v4 = *(const float4*)(src + voff + d4);
            uint4 kp = make_uint4(f2tf(k4.x), f2tf(k4.y), f2tf(k4.z), f2tf(k4.w));
            uint4 vp = make_uint4(f2tf(v4.x), f2tf(v4.y), f2tf(v4.z), f2tf(v4.w));
            *(uint4*)&Ks[key * 68 + d4] = kp;
            *(uint4*)&Vs[key * 72 + d4] = vp;
        }
        __syncthreads();

        // S = Q @ K^T  (8 n-tiles of 8 keys, 8 k-steps of 8 dims)
        float S[8][4];
#pragma unroll
        for (int j = 0; j < 8; j++) { S[j][0] = S[j][1] = S[j][2] = S[j][3] = 0.f; }
#pragma unroll
        for (int j = 0; j < 8; j++) {
            const unsigned* kr = &Ks[(8 * j + g) * 68];
#pragma unroll
            for (int t = 0; t < 8; t++) {
                unsigned b0 = kr[8 * t + c];
                unsigned b1 = kr[8 * t + c + 4];
                mma_tf32(S[j], Qf[t], b0, b1);
            }
        }

        // Causal mask (only tiles touching the diagonal for this warp)
        if (k0 + 63 > q0 + warp * 16) {
#pragma unroll
            for (int j = 0; j < 8; j++) {
                const int kk = k0 + 8 * j + 2 * c;
                if (kk     > qi0) S[j][0] = -1e30f;
                if (kk + 1 > qi0) S[j][1] = -1e30f;
                if (kk     > qi1) S[j][2] = -1e30f;
                if (kk + 1 > qi1) S[j][3] = -1e30f;
            }
        }

        // Online softmax (rows qi0 via elems 0,1; qi1 via 2,3)
        float mx0 = -1e30f, mx1 = -1e30f;
#pragma unroll
        for (int j = 0; j < 8; j++) {
            mx0 = fmaxf(mx0, fmaxf(S[j][0], S[j][1]));
            mx1 = fmaxf(mx1, fmaxf(S[j][2], S[j][3]));
        }
        mx0 = fmaxf(mx0, __shfl_xor_sync(0xffffffffu, mx0, 1));
        mx0 = fmaxf(mx0, __shfl_xor_sync(0xffffffffu, mx0, 2));
        mx1 = fmaxf(mx1, __shfl_xor_sync(0xffffffffu, mx1, 1));
        mx1 = fmaxf(mx1, __shfl_xor_sync(0xffffffffu, mx1, 2));

        const float mn0 = fmaxf(m0, mx0);
        const float mn1 = fmaxf(m1, mx1);
        const float corr0 = __expf(m0 - mn0);
        const float corr1 = __expf(m1 - mn1);
        m0 = mn0; m1 = mn1;

        float s0 = 0.f, s1 = 0.f;
#pragma unroll
        for (int j = 0; j < 8; j++) {
            S[j][0] = __expf(S[j][0] - mn0);
            S[j][1] = __expf(S[j][1] - mn0);
            S[j][2] = __expf(S[j][2] - mn1);
            S[j][3] = __expf(S[j][3] - mn1);
            s0 += S[j][0] + S[j][1];
            s1 += S[j][2] + S[j][3];
        }
        s0 += __shfl_xor_sync(0xffffffffu, s0, 1);
        s0 += __shfl_xor_sync(0xffffffffu, s0, 2);
        s1 += __shfl_xor_sync(0xffffffffu, s1, 1);
        s1 += __shfl_xor_sync(0xffffffffu, s1, 2);
        l0 = l0 * corr0 + s0;
        l1 = l1 * corr1 + s1;

#pragma unroll
        for (int j = 0; j < 8; j++) {
            Of[j][0] *= corr0; Of[j][1] *= corr0;
            Of[j][2] *= corr1; Of[j][3] *= corr1;
        }

        // O += P @ V : k-step t over keys 8t..8t+7.
        // P acc-layout -> A-frag layout via quad shuffles.
#pragma unroll
        for (int t = 0; t < 8; t++) {
            float x0 = __shfl_sync(0xffffffffu, S[t][0], srcA);
            float x1 = __shfl_sync(0xffffffffu, S[t][1], srcA);
            float x2 = __shfl_sync(0xffffffffu, S[t][2], srcA);
            float x3 = __shfl_sync(0xffffffffu, S[t][3], srcA);
            float z0 = __shfl_sync(0xffffffffu, S[t][0], srcB);
            float z1 = __shfl_sync(0xffffffffu, S[t][1], srcB);
            float z2 = __shfl_sync(0xffffffffu, S[t][2], srcB);
            float z3 = __shfl_sync(0xffffffffu, S[t][3], srcB);
            unsigned a[4];
            a[0] = f2tf(sel ? x1 : x0);   // (g,   8t+c)
            a[1] = f2tf(sel ? x3 : x2);   // (g+8, 8t+c)
            a[2] = f2tf(sel ? z1 : z0);   // (g,   8t+c+4)
            a[3] = f2tf(sel ? z3 : z2);   // (g+8, 8t+c+4)

            const unsigned* vr  = &Vs[(8 * t + c) * 72];
            const unsigned* vr4 = &Vs[(8 * t + c + 4) * 72];
#pragma unroll
            for (int j = 0; j < 8; j++) {
                unsigned b0 = vr[8 * j + g];
                unsigned b1 = vr4[8 * j + g];
                mma_tf32(Of[j], a, b0, b1);
            }
        }
    }

    // Epilogue: O /= l, write rows qi0 and qi1.
    const float inv0 = 1.0f / l0;
    const float inv1 = 1.0f / l1;
    float* y0p = y + ((size_t)(b * T_SEQ + qi0)) * C_EMB + h * HS;
    float* y1p = y + ((size_t)(b * T_SEQ + qi1)) * C_EMB + h * HS;
#pragma unroll
    for (int j = 0; j < 8; j++) {
        *(float2*)(y0p + 8 * j + 2 * c) = make_float2(Of[j][0] * inv0, Of[j][1] * inv0);
        *(float2*)(y1p + 8 * j + 2 * c) = make_float2(Of[j][2] * inv1, Of[j][3] * inv1);
    }
}

// ---------------------------------------------------------------------------
extern "C" void kernel_launch(void* const* d_in, const int* in_sizes, int n_in,
                              void* d_out, int out_size)
{
    const float* x      = (const float*)d_in[0];
    const float* w_attn = (const float*)d_in[1];
    const float* w_proj = (const float*)d_in[2];
    float* out = (float*)d_out;

    float* qkv = nullptr;
    float* y   = nullptr;
    cudaGetSymbolAddress((void**)&qkv, g_qkv);
    cudaGetSymbolAddress((void**)&y,   g_y);

    const int M = BATCH * T_SEQ;        // 8192
    const int C = C_EMB;                // 1024

    // 1) QKV projection: [8192,1024] @ [1024,3072]  (tf32 tensor cores)
    {
        dim3 grid((3 * C) / 128, M / 128);
        tf32_gemm<<<grid, 256>>>(x, w_attn, qkv, M, 3 * C, C);
    }
    // 2) Causal flash attention (tf32 tensor cores)
    {
        dim3 grid(T_SEQ / 128, NH, BATCH);
        attn_tc<<<grid, 256>>>(qkv, y);
    }
    // 3) Output projection: [8192,1024] @ [1024,1024]  (tf32 tensor cores)
    {
        dim3 grid(C / 128, M / 128);
        tf32_gemm<<<grid, 256>>>(y, w_proj, out, M, C, C);
    }
}

// round 15
// speedup vs baseline: 4.1613x; 1.1742x over previous
#include <cuda_runtime.h>
#include <cstdint>
#include <cstddef>

#define T_SEQ 2048
#define C_EMB 1024
#define NH    16
#define HS    64
#define BATCH 4

// Scratch (device globals — no runtime allocation allowed)
__device__ float g_qkv[(size_t)BATCH * T_SEQ * 3 * C_EMB]; // 96 MB
__device__ float g_y[(size_t)BATCH * T_SEQ * C_EMB];       // 32 MB

__device__ __forceinline__ unsigned f2tf(float f) {
    unsigned u;
    asm("cvt.rna.tf32.f32 %0, %1;" : "=r"(u) : "f"(f));
    return u;
}

__device__ __forceinline__ void mma_tf32(
    float* acc, const unsigned* a, unsigned b0, unsigned b1)
{
    asm volatile(
        "mma.sync.aligned.m16n8k8.row.col.f32.tf32.tf32.f32 "
        "{%0,%1,%2,%3}, {%4,%5,%6,%7}, {%8,%9}, {%0,%1,%2,%3};"
        : "+f"(acc[0]), "+f"(acc[1]), "+f"(acc[2]), "+f"(acc[3])
        : "r"(a[0]), "r"(a[1]), "r"(a[2]), "r"(a[3]), "r"(b0), "r"(b1));
}

// ---------------------------------------------------------------------------
// tf32 tensor-core GEMM: C[MxN] = A[MxK] @ B[KxN], all row-major fp32.
// Block tile 128x128x16, 128 threads (4 warps in 2x2), warp tile 64x64.
// Double-buffered smem, register prefetch, one sync per k-tile.
// Requires M%128==0, N%128==0, K%16==0.
// ---------------------------------------------------------------------------
__global__ __launch_bounds__(128) void tf32_gemm4(
    const float* __restrict__ A, const float* __restrict__ B,
    float* __restrict__ C, int M, int N, int K)
{
    constexpr int BK = 16;
    constexpr int PAD = 136; // bank bijection (8c+g) for fragment reads
    __shared__ unsigned As[2][BK][PAD];
    __shared__ unsigned Bs[2][BK][PAD];

    const int tid  = threadIdx.x;
    const int lane = tid & 31;
    const int warp = tid >> 5;
    const int wm = warp & 1;   // 0..1 (64-row slab)
    const int wn = warp >> 1;  // 0..1 (64-col slab)
    const int g = lane >> 2;   // 0..7
    const int c = lane & 3;    // 0..3

    const int row0 = blockIdx.y * 128;
    const int col0 = blockIdx.x * 128;

    // A loader: rows arow and arow+64, 8 floats (2 float4) each, col chunk acol
    const int arow = tid >> 1;            // 0..63
    const int acol = (tid & 1) * 8;       // 0 or 8
    const float* Ap0 = A + (size_t)(row0 + arow) * K + acol;
    const float* Ap1 = A + (size_t)(row0 + arow + 64) * K + acol;
    // B loader: warp w covers tile rows k = w + 4*it; lane covers 4 cols
    const float* Bp = B + col0 + lane * 4;

    float acc[4][8][4];
#pragma unroll
    for (int i = 0; i < 4; i++)
#pragma unroll
        for (int j = 0; j < 8; j++)
#pragma unroll
            for (int r = 0; r < 4; r++) acc[i][j][r] = 0.f;

    const int ntiles = K / BK;

    float4 aPF[4], bPF[4];
    // Prologue: load tile 0
    aPF[0] = *(const float4*)(Ap0);
    aPF[1] = *(const float4*)(Ap0 + 4);
    aPF[2] = *(const float4*)(Ap1);
    aPF[3] = *(const float4*)(Ap1 + 4);
#pragma unroll
    for (int it = 0; it < 4; it++)
        bPF[it] = *(const float4*)(Bp + (size_t)(warp + 4 * it) * N);

    // Store tile 0 into buffer 0
    {
        const float a0[8] = { aPF[0].x, aPF[0].y, aPF[0].z, aPF[0].w,
                              aPF[1].x, aPF[1].y, aPF[1].z, aPF[1].w };
        const float a1[8] = { aPF[2].x, aPF[2].y, aPF[2].z, aPF[2].w,
                              aPF[3].x, aPF[3].y, aPF[3].z, aPF[3].w };
#pragma unroll
        for (int e = 0; e < 8; e++) {
            As[0][acol + e][arow]      = f2tf(a0[e]);
            As[0][acol + e][arow + 64] = f2tf(a1[e]);
        }
#pragma unroll
        for (int it = 0; it < 4; it++) {
            uint4 p = make_uint4(f2tf(bPF[it].x), f2tf(bPF[it].y),
                                 f2tf(bPF[it].z), f2tf(bPF[it].w));
            *(uint4*)&Bs[0][warp + 4 * it][lane * 4] = p;
        }
    }

    for (int t = 0; t < ntiles; t++) {
        __syncthreads();
        const int buf = t & 1;

        // Prefetch next tile into registers (hidden under compute)
        if (t + 1 < ntiles) {
            const int k0 = (t + 1) * BK;
            aPF[0] = *(const float4*)(Ap0 + k0);
            aPF[1] = *(const float4*)(Ap0 + k0 + 4);
            aPF[2] = *(const float4*)(Ap1 + k0);
            aPF[3] = *(const float4*)(Ap1 + k0 + 4);
#pragma unroll
            for (int it = 0; it < 4; it++)
                bPF[it] = *(const float4*)(Bp + (size_t)(k0 + warp + 4 * it) * N);
        }

        // Compute: 2 k8 steps
#pragma unroll
        for (int s = 0; s < 2; s++) {
            const int kr = s * 8;
            unsigned aF[4][4];
            unsigned bF[8][2];
#pragma unroll
            for (int i = 0; i < 4; i++) {
                const int m = wm * 64 + i * 16 + g;
                aF[i][0] = As[buf][kr + c][m];
                aF[i][1] = As[buf][kr + c][m + 8];
                aF[i][2] = As[buf][kr + c + 4][m];
                aF[i][3] = As[buf][kr + c + 4][m + 8];
            }
#pragma unroll
            for (int j = 0; j < 8; j++) {
                const int n = wn * 64 + j * 8 + g;
                bF[j][0] = Bs[buf][kr + c][n];
                bF[j][1] = Bs[buf][kr + c + 4][n];
            }
#pragma unroll
            for (int i = 0; i < 4; i++)
#pragma unroll
                for (int j = 0; j < 8; j++)
                    mma_tf32(acc[i][j], aF[i], bF[j][0], bF[j][1]);
        }

        // Store prefetched tile into the other buffer
        if (t + 1 < ntiles) {
            const int nb = (t + 1) & 1;
            const float a0[8] = { aPF[0].x, aPF[0].y, aPF[0].z, aPF[0].w,
                                  aPF[1].x, aPF[1].y, aPF[1].z, aPF[1].w };
            const float a1[8] = { aPF[2].x, aPF[2].y, aPF[2].z, aPF[2].w,
                                  aPF[3].x, aPF[3].y, aPF[3].z, aPF[3].w };
#pragma unroll
            for (int e = 0; e < 8; e++) {
                As[nb][acol + e][arow]      = f2tf(a0[e]);
                As[nb][acol + e][arow + 64] = f2tf(a1[e]);
            }
#pragma unroll
            for (int it = 0; it < 4; it++) {
                uint4 p = make_uint4(f2tf(bPF[it].x), f2tf(bPF[it].y),
                                     f2tf(bPF[it].z), f2tf(bPF[it].w));
                *(uint4*)&Bs[nb][warp + 4 * it][lane * 4] = p;
            }
        }
    }

    // Epilogue
#pragma unroll
    for (int i = 0; i < 4; i++) {
        const int r = row0 + wm * 64 + i * 16 + g;
#pragma unroll
        for (int j = 0; j < 8; j++) {
            const int cc = col0 + wn * 64 + j * 8 + 2 * c;
            float2 lo = make_float2(acc[i][j][0], acc[i][j][1]);
            float2 hi = make_float2(acc[i][j][2], acc[i][j][3]);
            *(float2*)(C + (size_t)r * N + cc)       = lo;
            *(float2*)(C + (size_t)(r + 8) * N + cc) = hi;
        }
    }
}

// ---------------------------------------------------------------------------
// Tensor-core causal flash attention (tf32 mma.sync, fp32 softmax/accum).
// Block = 128 queries of one (b,h); 8 warps, each owns one m16 tile.
// ---------------------------------------------------------------------------
__global__ __launch_bounds__(256) void attn_tc(
    const float* __restrict__ qkv, float* __restrict__ y)
{
    const int b  = blockIdx.z;
    const int h  = blockIdx.y;
    const int q0 = blockIdx.x * 128;
    const int tid  = threadIdx.x;
    const int lane = tid & 31;
    const int warp = tid >> 5;
    const int g = lane >> 2;
    const int c = lane & 3;

    __shared__ __align__(16) unsigned Ks[64 * 68];
    __shared__ __align__(16) unsigned Vs[64 * 72];

    const float* base = qkv + (size_t)b * T_SEQ * 3 * C_EMB;
    const int koff = C_EMB + h * HS;
    const int voff = 2 * C_EMB + h * HS;

    unsigned Qf[8][4];
    {
        const float* qb = base + (size_t)(q0 + warp * 16) * 3 * C_EMB + h * HS;
        const int r0 = g * 3 * C_EMB;
        const int r1 = (g + 8) * 3 * C_EMB;
#pragma unroll
        for (int t = 0; t < 8; t++) {
            Qf[t][0] = f2tf(qb[r0 + 8 * t + c]     * 0.125f);
            Qf[t][1] = f2tf(qb[r1 + 8 * t + c]     * 0.125f);
            Qf[t][2] = f2tf(qb[r0 + 8 * t + c + 4] * 0.125f);
            Qf[t][3] = f2tf(qb[r1 + 8 * t + c + 4] * 0.125f);
        }
    }

    float Of[8][4];
#pragma unroll
    for (int j = 0; j < 8; j++)
#pragma unroll
        for (int r = 0; r < 4; r++) Of[j][r] = 0.f;

    float m0 = -1e30f, m1 = -1e30f, l0 = 0.f, l1 = 0.f;
    const int qi0 = q0 + warp * 16 + g;
    const int qi1 = qi0 + 8;

    const int srcA = (g << 2) + (c >> 1);
    const int srcB = srcA + 2;
    const bool sel = (c & 1) != 0;

    const int kv_end = q0 + 128;
    for (int k0 = 0; k0 < kv_end; k0 += 64) {
        __syncthreads();
#pragma unroll
        for (int i = 0; i < 4; i++) {
            int idx = tid + i * 256;
            int key = idx >> 4;
            int d4  = (idx & 15) << 2;
            const float* src = base + (size_t)(k0 + key) * 3 * C_EMB;
            float4 k4 = *(const float4*)(src + koff + d4);
            float4 v4 = *(const float4*)(src + voff + d4);
            uint4 kp = make_uint4(f2tf(k4.x), f2tf(k4.y), f2tf(k4.z), f2tf(k4.w));
            uint4 vp = make_uint4(f2tf(v4.x), f2tf(v4.y), f2tf(v4.z), f2tf(v4.w));
            *(uint4*)&Ks[key * 68 + d4] = kp;
            *(uint4*)&Vs[key * 72 + d4] = vp;
        }
        __syncthreads();

        float S[8][4];
#pragma unroll
        for (int j = 0; j < 8; j++) { S[j][0] = S[j][1] = S[j][2] = S[j][3] = 0.f; }
#pragma unroll
        for (int j = 0; j < 8; j++) {
            const unsigned* kr = &Ks[(8 * j + g) * 68];
#pragma unroll
            for (int t = 0; t < 8; t++) {
                unsigned b0 = kr[8 * t + c];
                unsigned b1 = kr[8 * t + c + 4];
                mma_tf32(S[j], Qf[t], b0, b1);
            }
        }

        if (k0 + 63 > q0 + warp * 16) {
#pragma unroll
            for (int j = 0; j < 8; j++) {
                const int kk = k0 + 8 * j + 2 * c;
                if (kk     > qi0) S[j][0] = -1e30f;
                if (kk + 1 > qi0) S[j][1] = -1e30f;
                if (kk     > qi1) S[j][2] = -1e30f;
                if (kk + 1 > qi1) S[j][3] = -1e30f;
            }
        }

        float mx0 = -1e30f, mx1 = -1e30f;
#pragma unroll
        for (int j = 0; j < 8; j++) {
            mx0 = fmaxf(mx0, fmaxf(S[j][0], S[j][1]));
            mx1 = fmaxf(mx1, fmaxf(S[j][2], S[j][3]));
        }
        mx0 = fmaxf(mx0, __shfl_xor_sync(0xffffffffu, mx0, 1));
        mx0 = fmaxf(mx0, __shfl_xor_sync(0xffffffffu, mx0, 2));
        mx1 = fmaxf(mx1, __shfl_xor_sync(0xffffffffu, mx1, 1));
        mx1 = fmaxf(mx1, __shfl_xor_sync(0xffffffffu, mx1, 2));

        const float mn0 = fmaxf(m0, mx0);
        const float mn1 = fmaxf(m1, mx1);
        const float corr0 = __expf(m0 - mn0);
        const float corr1 = __expf(m1 - mn1);
        m0 = mn0; m1 = mn1;

        float s0 = 0.f, s1 = 0.f;
#pragma unroll
        for (int j = 0; j < 8; j++) {
            S[j][0] = __expf(S[j][0] - mn0);
            S[j][1] = __expf(S[j][1] - mn0);
            S[j][2] = __expf(S[j][2] - mn1);
            S[j][3] = __expf(S[j][3] - mn1);
            s0 += S[j][0] + S[j][1];
            s1 += S[j][2] + S[j][3];
        }
        s0 += __shfl_xor_sync(0xffffffffu, s0, 1);
        s0 += __shfl_xor_sync(0xffffffffu, s0, 2);
        s1 += __shfl_xor_sync(0xffffffffu, s1, 1);
        s1 += __shfl_xor_sync(0xffffffffu, s1, 2);
        l0 = l0 * corr0 + s0;
        l1 = l1 * corr1 + s1;

#pragma unroll
        for (int j = 0; j < 8; j++) {
            Of[j][0] *= corr0; Of[j][1] *= corr0;
            Of[j][2] *= corr1; Of[j][3] *= corr1;
        }

#pragma unroll
        for (int t = 0; t < 8; t++) {
            float x0 = __shfl_sync(0xffffffffu, S[t][0], srcA);
            float x1 = __shfl_sync(0xffffffffu, S[t][1], srcA);
            float x2 = __shfl_sync(0xffffffffu, S[t][2], srcA);
            float x3 = __shfl_sync(0xffffffffu, S[t][3], srcA);
            float z0 = __shfl_sync(0xffffffffu, S[t][0], srcB);
            float z1 = __shfl_sync(0xffffffffu, S[t][1], srcB);
            float z2 = __shfl_sync(0xffffffffu, S[t][2], srcB);
            float z3 = __shfl_sync(0xffffffffu, S[t][3], srcB);
            unsigned a[4];
            a[0] = f2tf(sel ? x1 : x0);
            a[1] = f2tf(sel ? x3 : x2);
            a[2] = f2tf(sel ? z1 : z0);
            a[3] = f2tf(sel ? z3 : z2);

            const unsigned* vr  = &Vs[(8 * t + c) * 72];
            const unsigned* vr4 = &Vs[(8 * t + c + 4) * 72];
#pragma unroll
            for (int j = 0; j < 8; j++) {
                unsigned b0 = vr[8 * j + g];
                unsigned b1 = vr4[8 * j + g];
                mma_tf32(Of[j], a, b0, b1);
            }
        }
    }

    const float inv0 = 1.0f / l0;
    const float inv1 = 1.0f / l1;
    float* y0p = y + ((size_t)(b * T_SEQ + qi0)) * C_EMB + h * HS;
    float* y1p = y + ((size_t)(b * T_SEQ + qi1)) * C_EMB + h * HS;
#pragma unroll
    for (int j = 0; j < 8; j++) {
        *(float2*)(y0p + 8 * j + 2 * c) = make_float2(Of[j][0] * inv0, Of[j][1] * inv0);
        *(float2*)(y1p + 8 * j + 2 * c) = make_float2(Of[j][2] * inv1, Of[j][3] * inv1);
    }
}

// ---------------------------------------------------------------------------
extern "C" void kernel_launch(void* const* d_in, const int* in_sizes, int n_in,
                              void* d_out, int out_size)
{
    const float* x      = (const float*)d_in[0];
    const float* w_attn = (const float*)d_in[1];
    const float* w_proj = (const float*)d_in[2];
    float* out = (float*)d_out;

    float* qkv = nullptr;
    float* y   = nullptr;
    cudaGetSymbolAddress((void**)&qkv, g_qkv);
    cudaGetSymbolAddress((void**)&y,   g_y);

    const int M = BATCH * T_SEQ;        // 8192
    const int C = C_EMB;                // 1024

    // 1) QKV projection: [8192,1024] @ [1024,3072]  (tf32 tensor cores)
    {
        dim3 grid((3 * C) / 128, M / 128);
        tf32_gemm4<<<grid, 128>>>(x, w_attn, qkv, M, 3 * C, C);
    }
    // 2) Causal flash attention (tf32 tensor cores)
    {
        dim3 grid(T_SEQ / 128, NH, BATCH);
        attn_tc<<<grid, 256>>>(qkv, y);
    }
    // 3) Output projection: [8192,1024] @ [1024,1024]  (tf32 tensor cores)
    {
        dim3 grid(C / 128, M / 128);
        tf32_gemm4<<<grid, 128>>>(y, w_proj, out, M, C, C);
    }
}

// round 16
// speedup vs baseline: 4.5069x; 1.0831x over previous
#include <cuda_runtime.h>
#include <cstdint>
#include <cstddef>

#define T_SEQ 2048
#define C_EMB 1024
#define NH    16
#define HS    64
#define BATCH 4

// Scratch (device globals — no runtime allocation allowed)
__device__ float g_qkv[(size_t)BATCH * T_SEQ * 3 * C_EMB]; // 96 MB
__device__ float g_y[(size_t)BATCH * T_SEQ * C_EMB];       // 32 MB

__device__ __forceinline__ unsigned f2tf(float f) {
    unsigned u;
    asm("cvt.rna.tf32.f32 %0, %1;" : "=r"(u) : "f"(f));
    return u;
}

__device__ __forceinline__ void mma_tf32(
    float* acc, const unsigned* a, unsigned b0, unsigned b1)
{
    asm volatile(
        "mma.sync.aligned.m16n8k8.row.col.f32.tf32.tf32.f32 "
        "{%0,%1,%2,%3}, {%4,%5,%6,%7}, {%8,%9}, {%0,%1,%2,%3};"
        : "+f"(acc[0]), "+f"(acc[1]), "+f"(acc[2]), "+f"(acc[3])
        : "r"(a[0]), "r"(a[1]), "r"(a[2]), "r"(a[3]), "r"(b0), "r"(b1));
}

// ---------------------------------------------------------------------------
// tf32 tensor-core GEMM: C[MxN] = A[MxK] @ B[KxN], all row-major fp32.
// Block tile 128x128x16, 128 threads (4 warps in 2x2), warp tile 64x64.
// Double-buffered smem, register prefetch, one sync per k-tile. (unchanged)
// ---------------------------------------------------------------------------
__global__ __launch_bounds__(128) void tf32_gemm4(
    const float* __restrict__ A, const float* __restrict__ B,
    float* __restrict__ C, int M, int N, int K)
{
    constexpr int BK = 16;
    constexpr int PAD = 136;
    __shared__ unsigned As[2][BK][PAD];
    __shared__ unsigned Bs[2][BK][PAD];

    const int tid  = threadIdx.x;
    const int lane = tid & 31;
    const int warp = tid >> 5;
    const int wm = warp & 1;
    const int wn = warp >> 1;
    const int g = lane >> 2;
    const int c = lane & 3;

    const int row0 = blockIdx.y * 128;
    const int col0 = blockIdx.x * 128;

    const int arow = tid >> 1;
    const int acol = (tid & 1) * 8;
    const float* Ap0 = A + (size_t)(row0 + arow) * K + acol;
    const float* Ap1 = A + (size_t)(row0 + arow + 64) * K + acol;
    const float* Bp = B + col0 + lane * 4;

    float acc[4][8][4];
#pragma unroll
    for (int i = 0; i < 4; i++)
#pragma unroll
        for (int j = 0; j < 8; j++)
#pragma unroll
            for (int r = 0; r < 4; r++) acc[i][j][r] = 0.f;

    const int ntiles = K / BK;

    float4 aPF[4], bPF[4];
    aPF[0] = *(const float4*)(Ap0);
    aPF[1] = *(const float4*)(Ap0 + 4);
    aPF[2] = *(const float4*)(Ap1);
    aPF[3] = *(const float4*)(Ap1 + 4);
#pragma unroll
    for (int it = 0; it < 4; it++)
        bPF[it] = *(const float4*)(Bp + (size_t)(warp + 4 * it) * N);

    {
        const float a0[8] = { aPF[0].x, aPF[0].y, aPF[0].z, aPF[0].w,
                              aPF[1].x, aPF[1].y, aPF[1].z, aPF[1].w };
        const float a1[8] = { aPF[2].x, aPF[2].y, aPF[2].z, aPF[2].w,
                              aPF[3].x, aPF[3].y, aPF[3].z, aPF[3].w };
#pragma unroll
        for (int e = 0; e < 8; e++) {
            As[0][acol + e][arow]      = f2tf(a0[e]);
            As[0][acol + e][arow + 64] = f2tf(a1[e]);
        }
#pragma unroll
        for (int it = 0; it < 4; it++) {
            uint4 p = make_uint4(f2tf(bPF[it].x), f2tf(bPF[it].y),
                                 f2tf(bPF[it].z), f2tf(bPF[it].w));
            *(uint4*)&Bs[0][warp + 4 * it][lane * 4] = p;
        }
    }

    for (int t = 0; t < ntiles; t++) {
        __syncthreads();
        const int buf = t & 1;

        if (t + 1 < ntiles) {
            const int k0 = (t + 1) * BK;
            aPF[0] = *(const float4*)(Ap0 + k0);
            aPF[1] = *(const float4*)(Ap0 + k0 + 4);
            aPF[2] = *(const float4*)(Ap1 + k0);
            aPF[3] = *(const float4*)(Ap1 + k0 + 4);
#pragma unroll
            for (int it = 0; it < 4; it++)
                bPF[it] = *(const float4*)(Bp + (size_t)(k0 + warp + 4 * it) * N);
        }

#pragma unroll
        for (int s = 0; s < 2; s++) {
            const int kr = s * 8;
            unsigned aF[4][4];
            unsigned bF[8][2];
#pragma unroll
            for (int i = 0; i < 4; i++) {
                const int m = wm * 64 + i * 16 + g;
                aF[i][0] = As[buf][kr + c][m];
                aF[i][1] = As[buf][kr + c][m + 8];
                aF[i][2] = As[buf][kr + c + 4][m];
                aF[i][3] = As[buf][kr + c + 4][m + 8];
            }
#pragma unroll
            for (int j = 0; j < 8; j++) {
                const int n = wn * 64 + j * 8 + g;
                bF[j][0] = Bs[buf][kr + c][n];
                bF[j][1] = Bs[buf][kr + c + 4][n];
            }
#pragma unroll
            for (int i = 0; i < 4; i++)
#pragma unroll
                for (int j = 0; j < 8; j++)
                    mma_tf32(acc[i][j], aF[i], bF[j][0], bF[j][1]);
        }

        if (t + 1 < ntiles) {
            const int nb = (t + 1) & 1;
            const float a0[8] = { aPF[0].x, aPF[0].y, aPF[0].z, aPF[0].w,
                                  aPF[1].x, aPF[1].y, aPF[1].z, aPF[1].w };
            const float a1[8] = { aPF[2].x, aPF[2].y, aPF[2].z, aPF[2].w,
                                  aPF[3].x, aPF[3].y, aPF[3].z, aPF[3].w };
#pragma unroll
            for (int e = 0; e < 8; e++) {
                As[nb][acol + e][arow]      = f2tf(a0[e]);
                As[nb][acol + e][arow + 64] = f2tf(a1[e]);
            }
#pragma unroll
            for (int it = 0; it < 4; it++) {
                uint4 p = make_uint4(f2tf(bPF[it].x), f2tf(bPF[it].y),
                                     f2tf(bPF[it].z), f2tf(bPF[it].w));
                *(uint4*)&Bs[nb][warp + 4 * it][lane * 4] = p;
            }
        }
    }

#pragma unroll
    for (int i = 0; i < 4; i++) {
        const int r = row0 + wm * 64 + i * 16 + g;
#pragma unroll
        for (int j = 0; j < 8; j++) {
            const int cc = col0 + wn * 64 + j * 8 + 2 * c;
            float2 lo = make_float2(acc[i][j][0], acc[i][j][1]);
            float2 hi = make_float2(acc[i][j][2], acc[i][j][3]);
            *(float2*)(C + (size_t)r * N + cc)       = lo;
            *(float2*)(C + (size_t)(r + 8) * N + cc) = hi;
        }
    }
}

// ---------------------------------------------------------------------------
// Tensor-core causal flash attention (tf32 mma.sync, fp32 softmax/accum).
// Block = 128 queries of one (b,h); 4 warps, each owns TWO m16 tiles (32 rows)
// so K/V fragment LDS is shared across both tiles (2x reuse vs round 10).
// ---------------------------------------------------------------------------
__global__ __launch_bounds__(128) void attn_tc(
    const float* __restrict__ qkv, float* __restrict__ y)
{
    const int b  = blockIdx.z;
    const int h  = blockIdx.y;
    const int q0 = blockIdx.x * 128;
    const int tid  = threadIdx.x;
    const int lane = tid & 31;
    const int warp = tid >> 5;   // 0..3, owns rows q0+warp*32 .. +31
    const int g = lane >> 2;
    const int c = lane & 3;

    __shared__ __align__(16) unsigned Ks[64 * 68];
    __shared__ __align__(16) unsigned Vs[64 * 72];

    const float* base = qkv + (size_t)b * T_SEQ * 3 * C_EMB;
    const int koff = C_EMB + h * HS;
    const int voff = 2 * C_EMB + h * HS;

    // Q fragments for two m16 tiles, pre-scaled by 1/8, tf32.
    unsigned Qf[2][8][4];
#pragma unroll
    for (int ii = 0; ii < 2; ii++) {
        const float* qb = base + (size_t)(q0 + warp * 32 + ii * 16) * 3 * C_EMB + h * HS;
        const int r0 = g * 3 * C_EMB;
        const int r1 = (g + 8) * 3 * C_EMB;
#pragma unroll
        for (int t = 0; t < 8; t++) {
            Qf[ii][t][0] = f2tf(qb[r0 + 8 * t + c]     * 0.125f);
            Qf[ii][t][1] = f2tf(qb[r1 + 8 * t + c]     * 0.125f);
            Qf[ii][t][2] = f2tf(qb[r0 + 8 * t + c + 4] * 0.125f);
            Qf[ii][t][3] = f2tf(qb[r1 + 8 * t + c + 4] * 0.125f);
        }
    }

    float Of[2][8][4];
#pragma unroll
    for (int ii = 0; ii < 2; ii++)
#pragma unroll
        for (int j = 0; j < 8; j++)
#pragma unroll
            for (int r = 0; r < 4; r++) Of[ii][j][r] = 0.f;

    float mrow[2][2], lrow[2][2];
#pragma unroll
    for (int ii = 0; ii < 2; ii++) {
        mrow[ii][0] = mrow[ii][1] = -1e30f;
        lrow[ii][0] = lrow[ii][1] = 0.f;
    }

    const int srcA = (g << 2) + (c >> 1);
    const int srcB = srcA + 2;
    const bool sel = (c & 1) != 0;

    const int kv_end = q0 + 128;
    for (int k0 = 0; k0 < kv_end; k0 += 64) {
        __syncthreads();
        // Cooperative K/V tile load: 64 keys x 64 dims, tf32-converted.
#pragma unroll
        for (int i = 0; i < 8; i++) {
            int idx = tid + i * 128;        // 0..1023
            int key = idx >> 4;             // 0..63
            int d4  = (idx & 15) << 2;      // 0..60
            const float* src = base + (size_t)(k0 + key) * 3 * C_EMB;
            float4 k4 = *(const float4*)(src + koff + d4);
            float4 v4 = *(const float4*)(src + voff + d4);
            uint4 kp = make_uint4(f2tf(k4.x), f2tf(k4.y), f2tf(k4.z), f2tf(k4.w));
            uint4 vp = make_uint4(f2tf(v4.x), f2tf(v4.y), f2tf(v4.z), f2tf(v4.w));
            *(uint4*)&Ks[key * 68 + d4] = kp;
            *(uint4*)&Vs[key * 72 + d4] = vp;
        }
        __syncthreads();

        // S = Q @ K^T — K fragments shared across both m16 tiles
        float S[2][8][4];
#pragma unroll
        for (int ii = 0; ii < 2; ii++)
#pragma unroll
            for (int j = 0; j < 8; j++)
                S[ii][j][0] = S[ii][j][1] = S[ii][j][2] = S[ii][j][3] = 0.f;
#pragma unroll
        for (int j = 0; j < 8; j++) {
            const unsigned* kr = &Ks[(8 * j + g) * 68];
#pragma unroll
            for (int t = 0; t < 8; t++) {
                unsigned b0 = kr[8 * t + c];
                unsigned b1 = kr[8 * t + c + 4];
                mma_tf32(S[0][j], Qf[0][t], b0, b1);
                mma_tf32(S[1][j], Qf[1][t], b0, b1);
            }
        }

        // Causal mask + online softmax per m16 tile
#pragma unroll
        for (int ii = 0; ii < 2; ii++) {
            const int qi0 = q0 + warp * 32 + ii * 16 + g;
            const int qi1 = qi0 + 8;

            if (k0 + 63 > q0 + warp * 32 + ii * 16) {
#pragma unroll
                for (int j = 0; j < 8; j++) {
                    const int kk = k0 + 8 * j + 2 * c;
                    if (kk     > qi0) S[ii][j][0] = -1e30f;
                    if (kk + 1 > qi0) S[ii][j][1] = -1e30f;
                    if (kk     > qi1) S[ii][j][2] = -1e30f;
                    if (kk + 1 > qi1) S[ii][j][3] = -1e30f;
                }
            }

            float mx0 = -1e30f, mx1 = -1e30f;
#pragma unroll
            for (int j = 0; j < 8; j++) {
                mx0 = fmaxf(mx0, fmaxf(S[ii][j][0], S[ii][j][1]));
                mx1 = fmaxf(mx1, fmaxf(S[ii][j][2], S[ii][j][3]));
            }
            mx0 = fmaxf(mx0, __shfl_xor_sync(0xffffffffu, mx0, 1));
            mx0 = fmaxf(mx0, __shfl_xor_sync(0xffffffffu, mx0, 2));
            mx1 = fmaxf(mx1, __shfl_xor_sync(0xffffffffu, mx1, 1));
            mx1 = fmaxf(mx1, __shfl_xor_sync(0xffffffffu, mx1, 2));

            const float mn0 = fmaxf(mrow[ii][0], mx0);
            const float mn1 = fmaxf(mrow[ii][1], mx1);
            const float corr0 = __expf(mrow[ii][0] - mn0);
            const float corr1 = __expf(mrow[ii][1] - mn1);
            mrow[ii][0] = mn0; mrow[ii][1] = mn1;

            float s0 = 0.f, s1 = 0.f;
#pragma unroll
            for (int j = 0; j < 8; j++) {
                S[ii][j][0] = __expf(S[ii][j][0] - mn0);
                S[ii][j][1] = __expf(S[ii][j][1] - mn0);
                S[ii][j][2] = __expf(S[ii][j][2] - mn1);
                S[ii][j][3] = __expf(S[ii][j][3] - mn1);
                s0 += S[ii][j][0] + S[ii][j][1];
                s1 += S[ii][j][2] + S[ii][j][3];
            }
            s0 += __shfl_xor_sync(0xffffffffu, s0, 1);
            s0 += __shfl_xor_sync(0xffffffffu, s0, 2);
            s1 += __shfl_xor_sync(0xffffffffu, s1, 1);
            s1 += __shfl_xor_sync(0xffffffffu, s1, 2);
            lrow[ii][0] = lrow[ii][0] * corr0 + s0;
            lrow[ii][1] = lrow[ii][1] * corr1 + s1;

#pragma unroll
            for (int j = 0; j < 8; j++) {
                Of[ii][j][0] *= corr0; Of[ii][j][1] *= corr0;
                Of[ii][j][2] *= corr1; Of[ii][j][3] *= corr1;
            }
        }

        // O += P @ V — V fragments shared across both m16 tiles
#pragma unroll
        for (int t = 0; t < 8; t++) {
            unsigned a[2][4];
#pragma unroll
            for (int ii = 0; ii < 2; ii++) {
                float x0 = __shfl_sync(0xffffffffu, S[ii][t][0], srcA);
                float x1 = __shfl_sync(0xffffffffu, S[ii][t][1], srcA);
                float x2 = __shfl_sync(0xffffffffu, S[ii][t][2], srcA);
                float x3 = __shfl_sync(0xffffffffu, S[ii][t][3], srcA);
                float z0 = __shfl_sync(0xffffffffu, S[ii][t][0], srcB);
                float z1 = __shfl_sync(0xffffffffu, S[ii][t][1], srcB);
                float z2 = __shfl_sync(0xffffffffu, S[ii][t][2], srcB);
                float z3 = __shfl_sync(0xffffffffu, S[ii][t][3], srcB);
                a[ii][0] = f2tf(sel ? x1 : x0);
                a[ii][1] = f2tf(sel ? x3 : x2);
                a[ii][2] = f2tf(sel ? z1 : z0);
                a[ii][3] = f2tf(sel ? z3 : z2);
            }

            const unsigned* vr  = &Vs[(8 * t + c) * 72];
            const unsigned* vr4 = &Vs[(8 * t + c + 4) * 72];
#pragma unroll
            for (int j = 0; j < 8; j++) {
                unsigned b0 = vr[8 * j + g];
                unsigned b1 = vr4[8 * j + g];
                mma_tf32(Of[0][j], a[0], b0, b1);
                mma_tf32(Of[1][j], a[1], b0, b1);
            }
        }
    }

    // Epilogue
#pragma unroll
    for (int ii = 0; ii < 2; ii++) {
        const int qi0 = q0 + warp * 32 + ii * 16 + g;
        const float inv0 = 1.0f / lrow[ii][0];
        const float inv1 = 1.0f / lrow[ii][1];
        float* y0p = y + ((size_t)(b * T_SEQ + qi0)) * C_EMB + h * HS;
        float* y1p = y + ((size_t)(b * T_SEQ + qi0 + 8)) * C_EMB + h * HS;
#pragma unroll
        for (int j = 0; j < 8; j++) {
            *(float2*)(y0p + 8 * j + 2 * c) =
                make_float2(Of[ii][j][0] * inv0, Of[ii][j][1] * inv0);
            *(float2*)(y1p + 8 * j + 2 * c) =
                make_float2(Of[ii][j][2] * inv1, Of[ii][j][3] * inv1);
        }
    }
}

// ---------------------------------------------------------------------------
extern "C" void kernel_launch(void* const* d_in, const int* in_sizes, int n_in,
                              void* d_out, int out_size)
{
    const float* x      = (const float*)d_in[0];
    const float* w_attn = (const float*)d_in[1];
    const float* w_proj = (const float*)d_in[2];
    float* out = (float*)d_out;

    float* qkv = nullptr;
    float* y   = nullptr;
    cudaGetSymbolAddress((void**)&qkv, g_qkv);
    cudaGetSymbolAddress((void**)&y,   g_y);

    const int M = BATCH * T_SEQ;        // 8192
    const int C = C_EMB;                // 1024

    // 1) QKV projection: [8192,1024] @ [1024,3072]  (tf32 tensor cores)
    {
        dim3 grid((3 * C) / 128, M / 128);
        tf32_gemm4<<<grid, 128>>>(x, w_attn, qkv, M, 3 * C, C);
    }
    // 2) Causal flash attention (tf32 tensor cores, 2 m16 tiles per warp)
    {
        dim3 grid(T_SEQ / 128, NH, BATCH);
        attn_tc<<<grid, 128>>>(qkv, y);
    }
    // 3) Output projection: [8192,1024] @ [1024,1024]  (tf32 tensor cores)
    {
        dim3 grid(C / 128, M / 128);
        tf32_gemm4<<<grid, 128>>>(y, w_proj, out, M, C, C);
    }
}

// round 17
// speedup vs baseline: 4.6987x; 1.0425x over previous
#include <cuda_runtime.h>
#include <cstdint>
#include <cstddef>

#define T_SEQ 2048
#define C_EMB 1024
#define NH    16
#define HS    64
#define BATCH 4

// Scratch (device globals — no runtime allocation allowed)
__device__ float g_qkv[(size_t)BATCH * T_SEQ * 3 * C_EMB]; // 96 MB
__device__ float g_y[(size_t)BATCH * T_SEQ * C_EMB];       // 32 MB
__device__ float g_xT[(size_t)C_EMB * (BATCH * T_SEQ)];    // 32 MB  x^T
__device__ float g_yT[(size_t)C_EMB * (BATCH * T_SEQ)];    // 32 MB  y^T

__device__ __forceinline__ unsigned f2tf(float f) {
    unsigned u;
    asm("cvt.rna.tf32.f32 %0, %1;" : "=r"(u) : "f"(f));
    return u;
}

__device__ __forceinline__ void mma_tf32(
    float* acc, const unsigned* a, unsigned b0, unsigned b1)
{
    asm volatile(
        "mma.sync.aligned.m16n8k8.row.col.f32.tf32.tf32.f32 "
        "{%0,%1,%2,%3}, {%4,%5,%6,%7}, {%8,%9}, {%0,%1,%2,%3};"
        : "+f"(acc[0]), "+f"(acc[1]), "+f"(acc[2]), "+f"(acc[3])
        : "r"(a[0]), "r"(a[1]), "r"(a[2]), "r"(a[3]), "r"(b0), "r"(b1));
}

// ---------------------------------------------------------------------------
// Transpose: out[C][R] = in[R][C].  Block (32,8), tile 32x32, smem pad 33.
// ---------------------------------------------------------------------------
__global__ __launch_bounds__(256) void transpose_k(
    const float* __restrict__ in, float* __restrict__ out, int R, int C)
{
    __shared__ float t[32][33];
    const int tx = threadIdx.x, ty = threadIdx.y;
    const int x0 = blockIdx.x * 32;
    const int y0 = blockIdx.y * 32;
#pragma unroll
    for (int i = 0; i < 4; i++)
        t[ty + 8 * i][tx] = in[(size_t)(y0 + ty + 8 * i) * C + x0 + tx];
    __syncthreads();
#pragma unroll
    for (int i = 0; i < 4; i++)
        out[(size_t)(x0 + ty + 8 * i) * R + y0 + tx] = t[tx][ty + 8 * i];
}

// ---------------------------------------------------------------------------
// tf32 tensor-core GEMM reading A TRANSPOSED: C[MxN] = A^T' where
// AT is [K][M] row-major;  B [KxN] row-major;  C [MxN] row-major.
// Block tile 128x128x16, 128 threads (4 warps 2x2), warp tile 64x64.
// Coalesced A loads (the round-15 kernel's A gather was the bottleneck).
// ---------------------------------------------------------------------------
__global__ __launch_bounds__(128) void tf32_gemm4T(
    const float* __restrict__ AT, const float* __restrict__ B,
    float* __restrict__ C, int M, int N, int K)
{
    constexpr int BK = 16;
    constexpr int PAD = 136;
    __shared__ unsigned As[2][BK][PAD];
    __shared__ unsigned Bs[2][BK][PAD];

    const int tid  = threadIdx.x;
    const int lane = tid & 31;
    const int warp = tid >> 5;
    const int wm = warp & 1;
    const int wn = warp >> 1;
    const int g = lane >> 2;
    const int c = lane & 3;

    const int row0 = blockIdx.y * 128;
    const int col0 = blockIdx.x * 128;

    // A loader (coalesced): kr = tid>>3 (0..15), ml = (tid&7)*4; 4 chunks m = ml+32i
    const int kr = tid >> 3;
    const int ml = (tid & 7) * 4;
    const float* Abase = AT + (size_t)kr * M + row0 + ml;
    // B loader: warp w covers tile rows k = w + 4*it; lane covers 4 cols
    const float* Bp = B + col0 + lane * 4;

    float acc[4][8][4];
#pragma unroll
    for (int i = 0; i < 4; i++)
#pragma unroll
        for (int j = 0; j < 8; j++)
#pragma unroll
            for (int r = 0; r < 4; r++) acc[i][j][r] = 0.f;

    const int ntiles = K / BK;

    float4 aPF[4], bPF[4];
#pragma unroll
    for (int i = 0; i < 4; i++)
        aPF[i] = *(const float4*)(Abase + 32 * i);
#pragma unroll
    for (int it = 0; it < 4; it++)
        bPF[it] = *(const float4*)(Bp + (size_t)(warp + 4 * it) * N);

    // Store tile 0 into buffer 0
#pragma unroll
    for (int i = 0; i < 4; i++) {
        uint4 p = make_uint4(f2tf(aPF[i].x), f2tf(aPF[i].y),
                             f2tf(aPF[i].z), f2tf(aPF[i].w));
        *(uint4*)&As[0][kr][ml + 32 * i] = p;
    }
#pragma unroll
    for (int it = 0; it < 4; it++) {
        uint4 p = make_uint4(f2tf(bPF[it].x), f2tf(bPF[it].y),
                             f2tf(bPF[it].z), f2tf(bPF[it].w));
        *(uint4*)&Bs[0][warp + 4 * it][lane * 4] = p;
    }

    for (int t = 0; t < ntiles; t++) {
        __syncthreads();
        const int buf = t & 1;

        // Prefetch next tile into registers (hidden under compute)
        if (t + 1 < ntiles) {
            const int k0 = (t + 1) * BK;
            const float* ap = Abase + (size_t)k0 * M;
#pragma unroll
            for (int i = 0; i < 4; i++)
                aPF[i] = *(const float4*)(ap + 32 * i);
#pragma unroll
            for (int it = 0; it < 4; it++)
                bPF[it] = *(const float4*)(Bp + (size_t)(k0 + warp + 4 * it) * N);
        }

        // Compute: 2 k8 steps
#pragma unroll
        for (int s = 0; s < 2; s++) {
            const int krr = s * 8;
            unsigned aF[4][4];
            unsigned bF[8][2];
#pragma unroll
            for (int i = 0; i < 4; i++) {
                const int m = wm * 64 + i * 16 + g;
                aF[i][0] = As[buf][krr + c][m];
                aF[i][1] = As[buf][krr + c][m + 8];
                aF[i][2] = As[buf][krr + c + 4][m];
                aF[i][3] = As[buf][krr + c + 4][m + 8];
            }
#pragma unroll
            for (int j = 0; j < 8; j++) {
                const int n = wn * 64 + j * 8 + g;
                bF[j][0] = Bs[buf][krr + c][n];
                bF[j][1] = Bs[buf][krr + c + 4][n];
            }
#pragma unroll
            for (int i = 0; i < 4; i++)
#pragma unroll
                for (int j = 0; j < 8; j++)
                    mma_tf32(acc[i][j], aF[i], bF[j][0], bF[j][1]);
        }

        // Store prefetched tile into the other buffer
        if (t + 1 < ntiles) {
            const int nb = (t + 1) & 1;
#pragma unroll
            for (int i = 0; i < 4; i++) {
                uint4 p = make_uint4(f2tf(aPF[i].x), f2tf(aPF[i].y),
                                     f2tf(aPF[i].z), f2tf(aPF[i].w));
                *(uint4*)&As[nb][kr][ml + 32 * i] = p;
            }
#pragma unroll
            for (int it = 0; it < 4; it++) {
                uint4 p = make_uint4(f2tf(bPF[it].x), f2tf(bPF[it].y),
                                     f2tf(bPF[it].z), f2tf(bPF[it].w));
                *(uint4*)&Bs[nb][warp + 4 * it][lane * 4] = p;
            }
        }
    }

    // Epilogue
#pragma unroll
    for (int i = 0; i < 4; i++) {
        const int r = row0 + wm * 64 + i * 16 + g;
#pragma unroll
        for (int j = 0; j < 8; j++) {
            const int cc = col0 + wn * 64 + j * 8 + 2 * c;
            float2 lo = make_float2(acc[i][j][0], acc[i][j][1]);
            float2 hi = make_float2(acc[i][j][2], acc[i][j][3]);
            *(float2*)(C + (size_t)r * N + cc)       = lo;
            *(float2*)(C + (size_t)(r + 8) * N + cc) = hi;
        }
    }
}

// ---------------------------------------------------------------------------
// Tensor-core causal flash attention (tf32 mma.sync, fp32 softmax/accum).
// Block = 128 queries of one (b,h); 4 warps, each owns TWO m16 tiles. (unchanged)
// ---------------------------------------------------------------------------
__global__ __launch_bounds__(128) void attn_tc(
    const float* __restrict__ qkv, float* __restrict__ y)
{
    const int b  = blockIdx.z;
    const int h  = blockIdx.y;
    const int q0 = blockIdx.x * 128;
    const int tid  = threadIdx.x;
    const int lane = tid & 31;
    const int warp = tid >> 5;
    const int g = lane >> 2;
    const int c = lane & 3;

    __shared__ __align__(16) unsigned Ks[64 * 68];
    __shared__ __align__(16) unsigned Vs[64 * 72];

    const float* base = qkv + (size_t)b * T_SEQ * 3 * C_EMB;
    const int koff = C_EMB + h * HS;
    const int voff = 2 * C_EMB + h * HS;

    unsigned Qf[2][8][4];
#pragma unroll
    for (int ii = 0; ii < 2; ii++) {
        const float* qb = base + (size_t)(q0 + warp * 32 + ii * 16) * 3 * C_EMB + h * HS;
        const int r0 = g * 3 * C_EMB;
        const int r1 = (g + 8) * 3 * C_EMB;
#pragma unroll
        for (int t = 0; t < 8; t++) {
            Qf[ii][t][0] = f2tf(qb[r0 + 8 * t + c]     * 0.125f);
            Qf[ii][t][1] = f2tf(qb[r1 + 8 * t + c]     * 0.125f);
            Qf[ii][t][2] = f2tf(qb[r0 + 8 * t + c + 4] * 0.125f);
            Qf[ii][t][3] = f2tf(qb[r1 + 8 * t + c + 4] * 0.125f);
        }
    }

    float Of[2][8][4];
#pragma unroll
    for (int ii = 0; ii < 2; ii++)
#pragma unroll
        for (int j = 0; j < 8; j++)
#pragma unroll
            for (int r = 0; r < 4; r++) Of[ii][j][r] = 0.f;

    float mrow[2][2], lrow[2][2];
#pragma unroll
    for (int ii = 0; ii < 2; ii++) {
        mrow[ii][0] = mrow[ii][1] = -1e30f;
        lrow[ii][0] = lrow[ii][1] = 0.f;
    }

    const int srcA = (g << 2) + (c >> 1);
    const int srcB = srcA + 2;
    const bool sel = (c & 1) != 0;

    const int kv_end = q0 + 128;
    for (int k0 = 0; k0 < kv_end; k0 += 64) {
        __syncthreads();
#pragma unroll
        for (int i = 0; i < 8; i++) {
            int idx = tid + i * 128;
            int key = idx >> 4;
            int d4  = (idx & 15) << 2;
            const float* src = base + (size_t)(k0 + key) * 3 * C_EMB;
            float4 k4 = *(const float4*)(src + koff + d4);
            float4 v4 = *(const float4*)(src + voff + d4);
            uint4 kp = make_uint4(f2tf(k4.x), f2tf(k4.y), f2tf(k4.z), f2tf(k4.w));
            uint4 vp = make_uint4(f2tf(v4.x), f2tf(v4.y), f2tf(v4.z), f2tf(v4.w));
            *(uint4*)&Ks[key * 68 + d4] = kp;
            *(uint4*)&Vs[key * 72 + d4] = vp;
        }
        __syncthreads();

        float S[2][8][4];
#pragma unroll
        for (int ii = 0; ii < 2; ii++)
#pragma unroll
            for (int j = 0; j < 8; j++)
                S[ii][j][0] = S[ii][j][1] = S[ii][j][2] = S[ii][j][3] = 0.f;
#pragma unroll
        for (int j = 0; j < 8; j++) {
            const unsigned* kr = &Ks[(8 * j + g) * 68];
#pragma unroll
            for (int t = 0; t < 8; t++) {
                unsigned b0 = kr[8 * t + c];
                unsigned b1 = kr[8 * t + c + 4];
                mma_tf32(S[0][j], Qf[0][t], b0, b1);
                mma_tf32(S[1][j], Qf[1][t], b0, b1);
            }
        }

#pragma unroll
        for (int ii = 0; ii < 2; ii++) {
            const int qi0 = q0 + warp * 32 + ii * 16 + g;
            const int qi1 = qi0 + 8;

            if (k0 + 63 > q0 + warp * 32 + ii * 16) {
#pragma unroll
                for (int j = 0; j < 8; j++) {
                    const int kk = k0 + 8 * j + 2 * c;
                    if (kk     > qi0) S[ii][j][0] = -1e30f;
                    if (kk + 1 > qi0) S[ii][j][1] = -1e30f;
                    if (kk     > qi1) S[ii][j][2] = -1e30f;
                    if (kk + 1 > qi1) S[ii][j][3] = -1e30f;
                }
            }

            float mx0 = -1e30f, mx1 = -1e30f;
#pragma unroll
            for (int j = 0; j < 8; j++) {
                mx0 = fmaxf(mx0, fmaxf(S[ii][j][0], S[ii][j][1]));
                mx1 = fmaxf(mx1, fmaxf(S[ii][j][2], S[ii][j][3]));
            }
            mx0 = fmaxf(mx0, __shfl_xor_sync(0xffffffffu, mx0, 1));
            mx0 = fmaxf(mx0, __shfl_xor_sync(0xffffffffu, mx0, 2));
            mx1 = fmaxf(mx1, __shfl_xor_sync(0xffffffffu, mx1, 1));
            mx1 = fmaxf(mx1, __shfl_xor_sync(0xffffffffu, mx1, 2));

            const float mn0 = fmaxf(mrow[ii][0], mx0);
            const float mn1 = fmaxf(mrow[ii][1], mx1);
            const float corr0 = __expf(mrow[ii][0] - mn0);
            const float corr1 = __expf(mrow[ii][1] - mn1);
            mrow[ii][0] = mn0; mrow[ii][1] = mn1;

            float s0 = 0.f, s1 = 0.f;
#pragma unroll
            for (int j = 0; j < 8; j++) {
                S[ii][j][0] = __expf(S[ii][j][0] - mn0);
                S[ii][j][1] = __expf(S[ii][j][1] - mn0);
                S[ii][j][2] = __expf(S[ii][j][2] - mn1);
                S[ii][j][3] = __expf(S[ii][j][3] - mn1);
                s0 += S[ii][j][0] + S[ii][j][1];
                s1 += S[ii][j][2] + S[ii][j][3];
            }
            s0 += __shfl_xor_sync(0xffffffffu, s0, 1);
            s0 += __shfl_xor_sync(0xffffffffu, s0, 2);
            s1 += __shfl_xor_sync(0xffffffffu, s1, 1);
            s1 += __shfl_xor_sync(0xffffffffu, s1, 2);
            lrow[ii][0] = lrow[ii][0] * corr0 + s0;
            lrow[ii][1] = lrow[ii][1] * corr1 + s1;

#pragma unroll
            for (int j = 0; j < 8; j++) {
                Of[ii][j][0] *= corr0; Of[ii][j][1] *= corr0;
                Of[ii][j][2] *= corr1; Of[ii][j][3] *= corr1;
            }
        }

#pragma unroll
        for (int t = 0; t < 8; t++) {
            unsigned a[2][4];
#pragma unroll
            for (int ii = 0; ii < 2; ii++) {
                float x0 = __shfl_sync(0xffffffffu, S[ii][t][0], srcA);
                float x1 = __shfl_sync(0xffffffffu, S[ii][t][1], srcA);
                float x2 = __shfl_sync(0xffffffffu, S[ii][t][2], srcA);
                float x3 = __shfl_sync(0xffffffffu, S[ii][t][3], srcA);
                float z0 = __shfl_sync(0xffffffffu, S[ii][t][0], srcB);
                float z1 = __shfl_sync(0xffffffffu, S[ii][t][1], srcB);
                float z2 = __shfl_sync(0xffffffffu, S[ii][t][2], srcB);
                float z3 = __shfl_sync(0xffffffffu, S[ii][t][3], srcB);
                a[ii][0] = f2tf(sel ? x1 : x0);
                a[ii][1] = f2tf(sel ? x3 : x2);
                a[ii][2] = f2tf(sel ? z1 : z0);
                a[ii][3] = f2tf(sel ? z3 : z2);
            }

            const unsigned* vr  = &Vs[(8 * t + c) * 72];
            const unsigned* vr4 = &Vs[(8 * t + c + 4) * 72];
#pragma unroll
            for (int j = 0; j < 8; j++) {
                unsigned b0 = vr[8 * j + g];
                unsigned b1 = vr4[8 * j + g];
                mma_tf32(Of[0][j], a[0], b0, b1);
                mma_tf32(Of[1][j], a[1], b0, b1);
            }
        }
    }

#pragma unroll
    for (int ii = 0; ii < 2; ii++) {
        const int qi0 = q0 + warp * 32 + ii * 16 + g;
        const float inv0 = 1.0f / lrow[ii][0];
        const float inv1 = 1.0f / lrow[ii][1];
        float* y0p = y + ((size_t)(b * T_SEQ + qi0)) * C_EMB + h * HS;
        float* y1p = y + ((size_t)(b * T_SEQ + qi0 + 8)) * C_EMB + h * HS;
#pragma unroll
        for (int j = 0; j < 8; j++) {
            *(float2*)(y0p + 8 * j + 2 * c) =
                make_float2(Of[ii][j][0] * inv0, Of[ii][j][1] * inv0);
            *(float2*)(y1p + 8 * j + 2 * c) =
                make_float2(Of[ii][j][2] * inv1, Of[ii][j][3] * inv1);
        }
    }
}

// ---------------------------------------------------------------------------
extern "C" void kernel_launch(void* const* d_in, const int* in_sizes, int n_in,
                              void* d_out, int out_size)
{
    const float* x      = (const float*)d_in[0];
    const float* w_attn = (const float*)d_in[1];
    const float* w_proj = (const float*)d_in[2];
    float* out = (float*)d_out;

    float *qkv = nullptr, *y = nullptr, *xT = nullptr, *yT = nullptr;
    cudaGetSymbolAddress((void**)&qkv, g_qkv);
    cudaGetSymbolAddress((void**)&y,   g_y);
    cudaGetSymbolAddress((void**)&xT,  g_xT);
    cudaGetSymbolAddress((void**)&yT,  g_yT);

    const int M = BATCH * T_SEQ;        // 8192
    const int C = C_EMB;                // 1024

    // 0) Transpose x -> xT  [C][M]
    {
        dim3 grid(C / 32, M / 32);
        transpose_k<<<grid, dim3(32, 8)>>>(x, xT, M, C);
    }
    // 1) QKV projection: [8192,1024] @ [1024,3072]  (tf32 TC, coalesced A^T)
    {
        dim3 grid((3 * C) / 128, M / 128);
        tf32_gemm4T<<<grid, 128>>>(xT, w_attn, qkv, M, 3 * C, C);
    }
    // 2) Causal flash attention (tf32 tensor cores)
    {
        dim3 grid(T_SEQ / 128, NH, BATCH);
        attn_tc<<<grid, 128>>>(qkv, y);
    }
    // 3) Transpose y -> yT
    {
        dim3 grid(C / 32, M / 32);
        transpose_k<<<grid, dim3(32, 8)>>>(y, yT, M, C);
    }
    // 4) Output projection: [8192,1024] @ [1024,1024]  (tf32 TC, coalesced A^T)
    {
        dim3 grid(C / 128, M / 128);
        tf32_gemm4T<<<grid, 128>>>(yT, w_proj, out, M, C, C);
    }
}